// round 11
// baseline (speedup 1.0000x reference)
#include <cuda_runtime.h>
#include <math.h>

#define H    2048
#define V    50257
#define LL   80
#define H4   (H/4)      // 512 float4 per H-length vector
#define G4H  (4*H)      // 8192 gate rows per matrix
#define GB   (G4H / 8)  // 1024 blocks per gate matrix
#define LB   ((V + 7) / 8)   // k_logits blocks = 6283

// ---------------- scratch (device globals — no allocation allowed) ----------
__device__ float g_attn_logits[LL];
__device__ float g_attn_applied[H];
__device__ float g_lstm_in[H];
__device__ float g_gp[2 * G4H];    // [0,4H): W_ih partial + b_ih ; [4H,8H): W_hh partial + b_hh
__device__ float g_h_new[H];
__device__ float g_logits[V];
__device__ float g_bmax[LB];
__device__ float g_bsum[LB];
__device__ unsigned g_done;        // ticket across k_wih + k_whh blocks (2*GB total)

// ---------------- streams/events (static init; no device alloc in launch) ---
static cudaStream_t g_s2;
static cudaEvent_t  g_ev_fork, g_ev_join;
namespace {
struct StreamInit {
    StreamInit() {
        cudaStreamCreateWithFlags(&g_s2, cudaStreamNonBlocking);
        cudaEventCreateWithFlags(&g_ev_fork, cudaEventDisableTiming);
        cudaEventCreateWithFlags(&g_ev_join, cudaEventDisableTiming);
    }
};
StreamInit g_stream_init;
}

// ---------------- helpers ----------------
__device__ __forceinline__ float warp_reduce_add(float v) {
    v += __shfl_xor_sync(0xffffffffu, v, 16);
    v += __shfl_xor_sync(0xffffffffu, v, 8);
    v += __shfl_xor_sync(0xffffffffu, v, 4);
    v += __shfl_xor_sync(0xffffffffu, v, 2);
    v += __shfl_xor_sync(0xffffffffu, v, 1);
    return v;
}
__device__ __forceinline__ float warp_reduce_max(float v) {
    v = fmaxf(v, __shfl_xor_sync(0xffffffffu, v, 16));
    v = fmaxf(v, __shfl_xor_sync(0xffffffffu, v, 8));
    v = fmaxf(v, __shfl_xor_sync(0xffffffffu, v, 4));
    v = fmaxf(v, __shfl_xor_sync(0xffffffffu, v, 2));
    v = fmaxf(v, __shfl_xor_sync(0xffffffffu, v, 1));
    return v;
}

// LSTM cell, run by the globally-last gate block (ticket pattern).
__device__ __forceinline__ void lstm_cell_tail(const float* __restrict__ c,
                                               int nthreads) {
    __shared__ bool s_last;
    int t = threadIdx.x;
    __threadfence();                         // make this block's gp writes visible
    __syncthreads();
    if (t == 0) {
        unsigned ticket = atomicAdd(&g_done, 1u);
        s_last = (ticket == 2u * GB - 1u);   // last of ALL wih+whh blocks
    }
    __syncthreads();
    if (s_last) {
        __threadfence();                     // acquire: see all other blocks' gp
        for (int j = t; j < H; j += nthreads) {
            float gi = g_gp[j]         + g_gp[G4H + j];
            float gf = g_gp[H + j]     + g_gp[G4H + H + j];
            float gg = g_gp[2 * H + j] + g_gp[G4H + 2 * H + j];
            float go = g_gp[3 * H + j] + g_gp[G4H + 3 * H + j];
            float si = 1.f / (1.f + expf(-gi));
            float sf = 1.f / (1.f + expf(-gf));
            float so = 1.f / (1.f + expf(-go));
            float cn = sf * __ldg(c + j) + si * tanhf(gg);
            g_h_new[j] = so * tanhf(cn);
        }
        __threadfence();
        if (t == 0) g_done = 0;              // reset for next replay (deterministic)
    }
}

// ---------------- A1: attention logits -------------------------------------
__global__ void k_attn_logits(const int* __restrict__ x,
                              const float* __restrict__ emb_W,
                              const float* __restrict__ h,
                              const float* __restrict__ attn_W,
                              const float* __restrict__ attn_b) {
    int l = blockIdx.x;
    int t = threadIdx.x;
    const float4* emb4 = (const float4*)(emb_W + (long)x[0] * H);
    const float4* h4   = (const float4*)h;
    const float4* wA   = (const float4*)(attn_W + (long)l * 2 * H);        // vs h0
    const float4* wB   = wA + H4;                                          // vs emb
    float acc = 0.f;
#pragma unroll 4
    for (int i = t; i < H4; i += 128) {
        float4 a = __ldg(wA + i), va = __ldg(h4 + i);
        float4 b = __ldg(wB + i), vb = __ldg(emb4 + i);
        acc = fmaf(a.x, va.x, acc); acc = fmaf(a.y, va.y, acc);
        acc = fmaf(a.z, va.z, acc); acc = fmaf(a.w, va.w, acc);
        acc = fmaf(b.x, vb.x, acc); acc = fmaf(b.y, vb.y, acc);
        acc = fmaf(b.z, vb.z, acc); acc = fmaf(b.w, vb.w, acc);
    }
    __shared__ float s[4];
    acc = warp_reduce_add(acc);
    if ((t & 31) == 0) s[t >> 5] = acc;
    __syncthreads();
    if (t == 0)
        g_attn_logits[l] = s[0] + s[1] + s[2] + s[3] + __ldg(attn_b + l);
}

// ---------------- A2: softmax (recomputed per block) + attn_applied ---------
__global__ void k_attn_apply(const float* __restrict__ enc,
                             float* __restrict__ out_attn) {
    __shared__ float w[LL];
    __shared__ float red[8];
    int t = threadIdx.x;

    float v = (t < LL) ? g_attn_logits[t] : -INFINITY;
    float m = warp_reduce_max(v);
    if ((t & 31) == 0) red[t >> 5] = m;
    __syncthreads();
    float blockmax = fmaxf(fmaxf(red[0], red[1]), fmaxf(red[2], red[3]));
    float e = (t < LL) ? expf(v - blockmax) : 0.f;
    float s = warp_reduce_add(e);
    __syncthreads();
    if ((t & 31) == 0) red[t >> 5] = s;
    __syncthreads();
    float blocksum = red[0] + red[1] + red[2] + red[3];
    if (t < LL) {
        float wt = e / blocksum;
        w[t] = wt;
        if (blockIdx.x == 0) out_attn[t] = wt;
    }
    __syncthreads();

    int k = blockIdx.x * blockDim.x + t;
    if (k < H) {
        float acc = 0.f;
#pragma unroll 8
        for (int l = 0; l < LL; ++l)
            acc = fmaf(w[l], __ldg(enc + (long)l * H + k), acc);
        g_attn_applied[k] = acc;
    }
}

// ---------------- B: lstm_in = relu(comb_W @ [emb; attn_applied] + b) -------
// 512 threads = 16 warps, 8 rows per block, TWO warps per row.
__global__ void k_combine(const int* __restrict__ x,
                          const float* __restrict__ emb_W,
                          const float* __restrict__ comb_W,
                          const float* __restrict__ comb_b) {
    __shared__ float4 vec[2 * H4];           // 16 KB: [emb ; attn_applied]
    __shared__ float part[16];
    int t = threadIdx.x;
    const float4* emb4 = (const float4*)(emb_W + (long)x[0] * H);
    const float4* ap4  = (const float4*)g_attn_applied;
    for (int i = t; i < H4; i += 512) {
        vec[i]      = __ldg(emb4 + i);
        vec[H4 + i] = ap4[i];
    }
    __syncthreads();

    int warp = t >> 5, lane = t & 31;
    int rloc = warp >> 1;                    // 0..7
    int half = warp & 1;                     // 0/1
    int row  = blockIdx.x * 8 + rloc;
    const float4* w = (const float4*)(comb_W + (long)row * 2 * H);
    float acc = 0.f;
#pragma unroll 8
    for (int i = lane + half * 32; i < 2 * H4; i += 64) {
        float4 a = __ldcs(w + i);
        float4 v = vec[i];
        acc = fmaf(a.x, v.x, acc);
        acc = fmaf(a.y, v.y, acc);
        acc = fmaf(a.z, v.z, acc);
        acc = fmaf(a.w, v.w, acc);
    }
    acc = warp_reduce_add(acc);
    if (lane == 0) part[warp] = acc;
    __syncthreads();
    if (t < 8) {
        int r = blockIdx.x * 8 + t;
        float d = part[2 * t] + part[2 * t + 1];
        g_lstm_in[r] = fmaxf(d + __ldg(comb_b + r), 0.f);
    }
}

// ---------------- C1b: W_hh gate partials (depends ONLY on input h) ---------
// Second stream; overlaps the whole attn/combine chain and k_wih.
__global__ void k_whh(const float* __restrict__ h,
                      const float* __restrict__ W_hh,
                      const float* __restrict__ b_hh,
                      const float* __restrict__ c) {
    __shared__ float4 vec[H4];               // 8 KB
    int t = threadIdx.x;
    const float4* vsrc = (const float4*)h;
    for (int i = t; i < H4; i += 256) vec[i] = __ldg(vsrc + i);
    __syncthreads();

    int warp = t >> 5, lane = t & 31;
    int row = blockIdx.x * 8 + warp;               // 0..8191
    const float4* w = (const float4*)(W_hh + (long)row * H);
    float acc = 0.f;
#pragma unroll 8
    for (int i = lane; i < H4; i += 32) {
        float4 a = __ldcs(w + i);
        float4 v = vec[i];
        acc = fmaf(a.x, v.x, acc);
        acc = fmaf(a.y, v.y, acc);
        acc = fmaf(a.z, v.z, acc);
        acc = fmaf(a.w, v.w, acc);
    }
    acc = warp_reduce_add(acc);
    if (lane == 0)
        g_gp[G4H + row] = acc + __ldg(b_hh + row);

    lstm_cell_tail(c, 256);                  // globally-last block runs the cell
}

// ---------------- C1a: W_ih gate partials (depends on lstm_in) --------------
__global__ void k_wih(const float* __restrict__ W_ih,
                      const float* __restrict__ b_ih,
                      const float* __restrict__ c) {
    __shared__ float4 vec[H4];               // 8 KB
    int t = threadIdx.x;
    const float4* vsrc = (const float4*)g_lstm_in;
    for (int i = t; i < H4; i += 256) vec[i] = vsrc[i];
    __syncthreads();

    int warp = t >> 5, lane = t & 31;
    int row = blockIdx.x * 8 + warp;               // 0..8191
    const float4* w = (const float4*)(W_ih + (long)row * H);
    float acc = 0.f;
#pragma unroll 8
    for (int i = lane; i < H4; i += 32) {
        float4 a = __ldcs(w + i);
        float4 v = vec[i];
        acc = fmaf(a.x, v.x, acc);
        acc = fmaf(a.y, v.y, acc);
        acc = fmaf(a.z, v.z, acc);
        acc = fmaf(a.w, v.w, acc);
    }
    acc = warp_reduce_add(acc);
    if (lane == 0)
        g_gp[row] = acc + __ldg(b_ih + row);

    lstm_cell_tail(c, 256);                  // globally-last block runs the cell
}

// ---------------- D: output projection + per-block softmax partials ---------
__global__ void k_logits(const float* __restrict__ out_W,
                         const float* __restrict__ out_b) {
    __shared__ float4 vec[H4];               // 8 KB
    __shared__ float srow[8];
    int t = threadIdx.x;
    const float4* hv = (const float4*)g_h_new;
    for (int i = t; i < H4; i += 256) vec[i] = hv[i];
    __syncthreads();

    int warp = t >> 5, lane = t & 31;
    int row = blockIdx.x * 8 + warp;
    float logit = -INFINITY;
    if (row < V) {
        const float4* w = (const float4*)(out_W + (long)row * H);
        float acc = 0.f;
#pragma unroll 8
        for (int i = lane; i < H4; i += 32) {
            float4 a = __ldcs(w + i);
            float4 v = vec[i];
            acc = fmaf(a.x, v.x, acc);
            acc = fmaf(a.y, v.y, acc);
            acc = fmaf(a.z, v.z, acc);
            acc = fmaf(a.w, v.w, acc);
        }
        acc = warp_reduce_add(acc);
        logit = acc + __ldg(out_b + row);
        if (lane == 0) g_logits[row] = logit;
    }
    if (lane == 0) srow[warp] = logit;       // -inf for invalid rows
    __syncthreads();
    if (t == 0) {
        float bm = srow[0];
#pragma unroll
        for (int i = 1; i < 8; ++i) bm = fmaxf(bm, srow[i]);
        float bs = 0.f;
#pragma unroll
        for (int i = 0; i < 8; ++i) bs += expf(srow[i] - bm);  // exp(-inf)=0
        g_bmax[blockIdx.x] = bm;
        g_bsum[blockIdx.x] = bs;
    }
}

// ---------------- E: merge partials (per block, L2-resident) + write --------
__global__ void k_write_logp(float* __restrict__ out) {   // 256 threads
    __shared__ float sm[8];
    __shared__ float s_shift;
    int t = threadIdx.x;

    float m = -INFINITY;
    for (int i = t; i < LB; i += 256) m = fmaxf(m, g_bmax[i]);
    float wm = warp_reduce_max(m);
    if ((t & 31) == 0) sm[t >> 5] = wm;
    __syncthreads();
    float M = sm[0];
#pragma unroll
    for (int i = 1; i < 8; ++i) M = fmaxf(M, sm[i]);

    float s = 0.f;
    for (int i = t; i < LB; i += 256) s += g_bsum[i] * expf(g_bmax[i] - M);
    float ws = warp_reduce_add(s);
    __syncthreads();
    if ((t & 31) == 0) sm[t >> 5] = ws;
    __syncthreads();
    if (t == 0) {
        float S = 0.f;
#pragma unroll
        for (int i = 0; i < 8; ++i) S += sm[i];
        s_shift = M + logf(S);
    }
    __syncthreads();
    float shift = s_shift;
    int i = blockIdx.x * blockDim.x + t;
    if (i < V) out[i] = g_logits[i] - shift;
}

// ---------------- launch -----------------------------------------------------
extern "C" void kernel_launch(void* const* d_in, const int* in_sizes, int n_in,
                              void* d_out, int out_size) {
    const int*   x      = (const int*)  d_in[0];
    const float* enc    = (const float*)d_in[1];
    const float* h      = (const float*)d_in[2];
    const float* c      = (const float*)d_in[3];
    const float* emb_W  = (const float*)d_in[4];
    const float* attn_W = (const float*)d_in[5];
    const float* attn_b = (const float*)d_in[6];
    const float* comb_W = (const float*)d_in[7];
    const float* comb_b = (const float*)d_in[8];
    const float* W_ih   = (const float*)d_in[9];
    const float* W_hh   = (const float*)d_in[10];
    const float* b_ih   = (const float*)d_in[11];
    const float* b_hh   = (const float*)d_in[12];
    const float* out_W  = (const float*)d_in[13];
    const float* out_b  = (const float*)d_in[14];
    float* out = (float*)d_out;

    // Fork: W_hh partials depend only on input h — full overlap with the
    // attn/combine chain AND k_wih. The LSTM cell runs inside whichever
    // gate block finishes last (ticket), so no separate cell launch.
    cudaEventRecord(g_ev_fork, 0);
    cudaStreamWaitEvent(g_s2, g_ev_fork, 0);
    k_whh<<<GB, 256, 0, g_s2>>>(h, W_hh, b_hh, c);
    cudaEventRecord(g_ev_join, g_s2);

    // Main-stream dependency chain.
    k_attn_logits<<<LL, 128>>>(x, emb_W, h, attn_W, attn_b);
    k_attn_apply<<<H / 256, 256>>>(enc, out + V);
    k_combine<<<H / 8, 512>>>(x, emb_W, comb_W, comb_b);
    k_wih<<<GB, 256>>>(W_ih, b_ih, c);

    // k_logits needs h_new complete: ordered after k_wih (stream) and k_whh (event).
    cudaStreamWaitEvent(0, g_ev_join, 0);
    k_logits<<<LB, 256>>>(out_W, out_b);
    k_write_logp<<<(V + 255) / 256, 256>>>(out);
}

// round 12
// speedup vs baseline: 1.0849x; 1.0849x over previous
#include <cuda_runtime.h>
#include <math.h>

#define H    2048
#define V    50257
#define LL   80
#define H4   (H/4)      // 512 float4 per H-length vector
#define G4H  (4*H)      // 8192 gate rows per matrix
#define GB   (G4H / 8)  // 1024 blocks per gate matrix
#define NRED 64         // partial-reduction blocks for log-softmax

// ---------------- scratch (device globals — no allocation allowed) ----------
__device__ float g_attn_logits[LL];
__device__ float g_attn_applied[H];
__device__ float g_lstm_in[H];
__device__ float g_gp[2 * G4H];    // [0,4H): W_ih partial + b_ih ; [4H,8H): W_hh partial + b_hh
__device__ float g_h_new[H];
__device__ float g_logits[V];
__device__ float g_pmax[NRED];
__device__ float g_psum[NRED];

// ---------------- streams/events (static init; no device alloc in launch) ---
static cudaStream_t g_s2;
static cudaEvent_t  g_ev_fork, g_ev_join;
namespace {
struct StreamInit {
    StreamInit() {
        cudaStreamCreateWithFlags(&g_s2, cudaStreamNonBlocking);
        cudaEventCreateWithFlags(&g_ev_fork, cudaEventDisableTiming);
        cudaEventCreateWithFlags(&g_ev_join, cudaEventDisableTiming);
    }
};
StreamInit g_stream_init;
}

// ---------------- helpers ----------------
__device__ __forceinline__ float warp_reduce_add(float v) {
    v += __shfl_xor_sync(0xffffffffu, v, 16);
    v += __shfl_xor_sync(0xffffffffu, v, 8);
    v += __shfl_xor_sync(0xffffffffu, v, 4);
    v += __shfl_xor_sync(0xffffffffu, v, 2);
    v += __shfl_xor_sync(0xffffffffu, v, 1);
    return v;
}
__device__ __forceinline__ float warp_reduce_max(float v) {
    v = fmaxf(v, __shfl_xor_sync(0xffffffffu, v, 16));
    v = fmaxf(v, __shfl_xor_sync(0xffffffffu, v, 8));
    v = fmaxf(v, __shfl_xor_sync(0xffffffffu, v, 4));
    v = fmaxf(v, __shfl_xor_sync(0xffffffffu, v, 2));
    v = fmaxf(v, __shfl_xor_sync(0xffffffffu, v, 1));
    return v;
}

// ---------------- A1: attention logits -------------------------------------
__global__ void k_attn_logits(const int* __restrict__ x,
                              const float* __restrict__ emb_W,
                              const float* __restrict__ h,
                              const float* __restrict__ attn_W,
                              const float* __restrict__ attn_b) {
    int l = blockIdx.x;
    int t = threadIdx.x;
    const float4* emb4 = (const float4*)(emb_W + (long)x[0] * H);
    const float4* h4   = (const float4*)h;
    const float4* wA   = (const float4*)(attn_W + (long)l * 2 * H);        // vs h0
    const float4* wB   = wA + H4;                                          // vs emb
    float acc = 0.f;
#pragma unroll 4
    for (int i = t; i < H4; i += 128) {
        float4 a = __ldg(wA + i), va = __ldg(h4 + i);
        float4 b = __ldg(wB + i), vb = __ldg(emb4 + i);
        acc = fmaf(a.x, va.x, acc); acc = fmaf(a.y, va.y, acc);
        acc = fmaf(a.z, va.z, acc); acc = fmaf(a.w, va.w, acc);
        acc = fmaf(b.x, vb.x, acc); acc = fmaf(b.y, vb.y, acc);
        acc = fmaf(b.z, vb.z, acc); acc = fmaf(b.w, vb.w, acc);
    }
    __shared__ float s[4];
    acc = warp_reduce_add(acc);
    if ((t & 31) == 0) s[t >> 5] = acc;
    __syncthreads();
    if (t == 0)
        g_attn_logits[l] = s[0] + s[1] + s[2] + s[3] + __ldg(attn_b + l);
}

// ---------------- A2: softmax (recomputed per block) + attn_applied ---------
__global__ void k_attn_apply(const float* __restrict__ enc,
                             float* __restrict__ out_attn) {
    __shared__ float w[LL];
    __shared__ float red[8];
    int t = threadIdx.x;

    float v = (t < LL) ? g_attn_logits[t] : -INFINITY;
    float m = warp_reduce_max(v);
    if ((t & 31) == 0) red[t >> 5] = m;
    __syncthreads();
    float blockmax = fmaxf(fmaxf(red[0], red[1]), fmaxf(red[2], red[3]));
    float e = (t < LL) ? expf(v - blockmax) : 0.f;
    float s = warp_reduce_add(e);
    __syncthreads();
    if ((t & 31) == 0) red[t >> 5] = s;
    __syncthreads();
    float blocksum = red[0] + red[1] + red[2] + red[3];
    if (t < LL) {
        float wt = e / blocksum;
        w[t] = wt;
        if (blockIdx.x == 0) out_attn[t] = wt;
    }
    __syncthreads();

    int k = blockIdx.x * blockDim.x + t;
    if (k < H) {
        float acc = 0.f;
#pragma unroll 8
        for (int l = 0; l < LL; ++l)
            acc = fmaf(w[l], __ldg(enc + (long)l * H + k), acc);
        g_attn_applied[k] = acc;
    }
}

// ---------------- B: lstm_in = relu(comb_W @ [emb; attn_applied] + b) -------
// 512 threads = 16 warps, 8 rows per block, TWO warps per row.
__global__ void k_combine(const int* __restrict__ x,
                          const float* __restrict__ emb_W,
                          const float* __restrict__ comb_W,
                          const float* __restrict__ comb_b) {
    __shared__ float4 vec[2 * H4];           // 16 KB: [emb ; attn_applied]
    __shared__ float part[16];
    int t = threadIdx.x;
    const float4* emb4 = (const float4*)(emb_W + (long)x[0] * H);
    const float4* ap4  = (const float4*)g_attn_applied;
    for (int i = t; i < H4; i += 512) {
        vec[i]      = __ldg(emb4 + i);
        vec[H4 + i] = ap4[i];
    }
    __syncthreads();

    int warp = t >> 5, lane = t & 31;
    int rloc = warp >> 1;                    // 0..7
    int half = warp & 1;                     // 0/1
    int row  = blockIdx.x * 8 + rloc;
    const float4* w = (const float4*)(comb_W + (long)row * 2 * H);
    float acc = 0.f;
#pragma unroll 8
    for (int i = lane + half * 32; i < 2 * H4; i += 64) {
        float4 a = __ldcs(w + i);
        float4 v = vec[i];
        acc = fmaf(a.x, v.x, acc);
        acc = fmaf(a.y, v.y, acc);
        acc = fmaf(a.z, v.z, acc);
        acc = fmaf(a.w, v.w, acc);
    }
    acc = warp_reduce_add(acc);
    if (lane == 0) part[warp] = acc;
    __syncthreads();
    if (t < 8) {
        int r = blockIdx.x * 8 + t;
        float d = part[2 * t] + part[2 * t + 1];
        g_lstm_in[r] = fmaxf(d + __ldg(comb_b + r), 0.f);
    }
}

// ---------------- C1b: W_hh gate partials (depends ONLY on input h) ---------
// Second stream, overlapped with the attention/combine chain AND k_wih.
__global__ void k_whh(const float* __restrict__ h,
                      const float* __restrict__ W_hh,
                      const float* __restrict__ b_hh) {
    __shared__ float4 vec[H4];               // 8 KB
    int t = threadIdx.x;
    const float4* vsrc = (const float4*)h;
    for (int i = t; i < H4; i += 256) vec[i] = __ldg(vsrc + i);
    __syncthreads();

    int warp = t >> 5, lane = t & 31;
    int row = blockIdx.x * 8 + warp;               // 0..8191
    const float4* w = (const float4*)(W_hh + (long)row * H);
    float acc = 0.f;
#pragma unroll 8
    for (int i = lane; i < H4; i += 32) {
        float4 a = __ldcs(w + i);
        float4 v = vec[i];
        acc = fmaf(a.x, v.x, acc);
        acc = fmaf(a.y, v.y, acc);
        acc = fmaf(a.z, v.z, acc);
        acc = fmaf(a.w, v.w, acc);
    }
    acc = warp_reduce_add(acc);
    if (lane == 0)
        g_gp[G4H + row] = acc + __ldg(b_hh + row);
}

// ---------------- C1a: W_ih gate partials (depends on lstm_in) --------------
__global__ void k_wih(const float* __restrict__ W_ih,
                      const float* __restrict__ b_ih) {
    __shared__ float4 vec[H4];               // 8 KB
    int t = threadIdx.x;
    const float4* vsrc = (const float4*)g_lstm_in;
    for (int i = t; i < H4; i += 256) vec[i] = vsrc[i];
    __syncthreads();

    int warp = t >> 5, lane = t & 31;
    int row = blockIdx.x * 8 + warp;               // 0..8191
    const float4* w = (const float4*)(W_ih + (long)row * H);
    float acc = 0.f;
#pragma unroll 8
    for (int i = lane; i < H4; i += 32) {
        float4 a = __ldcs(w + i);
        float4 v = vec[i];
        acc = fmaf(a.x, v.x, acc);
        acc = fmaf(a.y, v.y, acc);
        acc = fmaf(a.z, v.z, acc);
        acc = fmaf(a.w, v.w, acc);
    }
    acc = warp_reduce_add(acc);
    if (lane == 0)
        g_gp[row] = acc + __ldg(b_ih + row);
}

// ---------------- C2: LSTM cell elementwise (merges partials) ---------------
__global__ void k_cell(const float* __restrict__ c) {
    int j = blockIdx.x * blockDim.x + threadIdx.x;
    if (j < H) {
        float gi = g_gp[j]         + g_gp[G4H + j];
        float gf = g_gp[H + j]     + g_gp[G4H + H + j];
        float gg = g_gp[2 * H + j] + g_gp[G4H + 2 * H + j];
        float go = g_gp[3 * H + j] + g_gp[G4H + 3 * H + j];
        float si = 1.f / (1.f + expf(-gi));
        float sf = 1.f / (1.f + expf(-gf));
        float so = 1.f / (1.f + expf(-go));
        float cn = sf * __ldg(c + j) + si * tanhf(gg);
        g_h_new[j] = so * tanhf(cn);
    }
}

// ---------------- D: output projection (dominant GEMV) ----------------------
// 512 threads = 16 warps, 16 rows per block; fewer blocks / vector stagings.
__global__ void k_logits(const float* __restrict__ out_W,
                         const float* __restrict__ out_b) {
    __shared__ float4 vec[H4];               // 8 KB
    int t = threadIdx.x;
    const float4* hv = (const float4*)g_h_new;
    for (int i = t; i < H4; i += 512) vec[i] = hv[i];
    __syncthreads();

    int warp = t >> 5, lane = t & 31;
    int row = blockIdx.x * 16 + warp;
    if (row < V) {
        const float4* w = (const float4*)(out_W + (long)row * H);
        float acc = 0.f;
#pragma unroll 8
        for (int i = lane; i < H4; i += 32) {
            float4 a = __ldcs(w + i);
            float4 v = vec[i];
            acc = fmaf(a.x, v.x, acc);
            acc = fmaf(a.y, v.y, acc);
            acc = fmaf(a.z, v.z, acc);
            acc = fmaf(a.w, v.w, acc);
        }
        acc = warp_reduce_add(acc);
        if (lane == 0) g_logits[row] = acc + __ldg(out_b + row);
    }
}

// ---------------- E1: per-block local max + sum exp(x - local max) ----------
__global__ void k_red_partial() {                 // NRED blocks x 256
    int t = threadIdx.x;
    float m = -INFINITY;
    for (int i = blockIdx.x * 256 + t; i < V; i += NRED * 256)
        m = fmaxf(m, g_logits[i]);
    float wm = warp_reduce_max(m);
    __shared__ float sm[8];
    if ((t & 31) == 0) sm[t >> 5] = wm;
    __syncthreads();
    float bm = sm[0];
#pragma unroll
    for (int i = 1; i < 8; ++i) bm = fmaxf(bm, sm[i]);

    float s = 0.f;
    for (int i = blockIdx.x * 256 + t; i < V; i += NRED * 256)
        s += expf(g_logits[i] - bm);
    float ws = warp_reduce_add(s);
    __syncthreads();
    if ((t & 31) == 0) sm[t >> 5] = ws;
    __syncthreads();
    if (t == 0) {
        float r = 0.f;
#pragma unroll
        for (int i = 0; i < 8; ++i) r += sm[i];
        g_pmax[blockIdx.x] = bm;
        g_psum[blockIdx.x] = r;
    }
}

// ---------------- E2: merge partials (per block) + write logp ---------------
__global__ void k_write_logp(float* __restrict__ out) {   // grid covers V, 256 thr
    __shared__ float s_shift;
    int t = threadIdx.x;
    if (t < 32) {
        float mm = fmaxf(g_pmax[t], g_pmax[t + 32]);
        mm = warp_reduce_max(mm);
        float ss = g_psum[t] * expf(g_pmax[t] - mm)
                 + g_psum[t + 32] * expf(g_pmax[t + 32] - mm);
        ss = warp_reduce_add(ss);
        if (t == 0) s_shift = mm + logf(ss);
    }
    __syncthreads();
    float shift = s_shift;
    int i = blockIdx.x * blockDim.x + t;
    if (i < V) out[i] = g_logits[i] - shift;
}

// ---------------- launch -----------------------------------------------------
extern "C" void kernel_launch(void* const* d_in, const int* in_sizes, int n_in,
                              void* d_out, int out_size) {
    const int*   x      = (const int*)  d_in[0];
    const float* enc    = (const float*)d_in[1];
    const float* h      = (const float*)d_in[2];
    const float* c      = (const float*)d_in[3];
    const float* emb_W  = (const float*)d_in[4];
    const float* attn_W = (const float*)d_in[5];
    const float* attn_b = (const float*)d_in[6];
    const float* comb_W = (const float*)d_in[7];
    const float* comb_b = (const float*)d_in[8];
    const float* W_ih   = (const float*)d_in[9];
    const float* W_hh   = (const float*)d_in[10];
    const float* b_ih   = (const float*)d_in[11];
    const float* b_hh   = (const float*)d_in[12];
    const float* out_W  = (const float*)d_in[13];
    const float* out_b  = (const float*)d_in[14];
    float* out = (float*)d_out;

    // Fork: W_hh partials depend only on input h — overlap with attn chain
    // AND with k_wih; join only before the cell.
    cudaEventRecord(g_ev_fork, 0);
    cudaStreamWaitEvent(g_s2, g_ev_fork, 0);
    k_whh<<<GB, 256, 0, g_s2>>>(h, W_hh, b_hh);
    cudaEventRecord(g_ev_join, g_s2);

    // Main-stream dependency chain.
    k_attn_logits<<<LL, 128>>>(x, emb_W, h, attn_W, attn_b);
    k_attn_apply<<<H / 256, 256>>>(enc, out + V);
    k_combine<<<H / 8, 512>>>(x, emb_W, comb_W, comb_b);
    k_wih<<<GB, 256>>>(W_ih, b_ih);

    // Join before the cell combines both gate partials.
    cudaStreamWaitEvent(0, g_ev_join, 0);
    k_cell<<<(H + 255) / 256, 256>>>(c);
    k_logits<<<(V + 15) / 16, 512>>>(out_W, out_b);
    k_red_partial<<<NRED, 256>>>();
    k_write_logp<<<(V + 255) / 256, 256>>>(out);
}